// round 9
// baseline (speedup 1.0000x reference)
#include <cuda_runtime.h>

#define N_NODES 50000
#define N_EDGES 600000
#define N_LABEL 200000
#define CH      128

#define CB_BLOCKS 196     // 196*256 = 50176 >= N_NODES ; all resident
#define CB_TPB    256
#define CB_THREADS (CB_BLOCKS * CB_TPB)

// ---------------- device scratch (zero at load; self-restoring) -------------
__device__ int   g_bar[3];                 // barrier counters (self-reset)
__device__ int   g_indeg [N_NODES];
__device__ int   g_cursor[N_NODES];
__device__ int   g_scan_state[CB_BLOCKS];
__device__ int   g_scan_agg  [CB_BLOCKS];
__device__ int   g_offs  [N_NODES + 1];
__device__ float g_dinv  [N_NODES];
__device__ int2  g_csr   [N_EDGES];        // .x = src, .y = float bits of w
__device__ float g_hA  [N_NODES * CH];
__device__ float g_z   [N_NODES * CH];

// ---------------- f32x2 packed helpers --------------------------------------
__device__ __forceinline__ void fma2(unsigned long long& d,
                                     unsigned long long a,
                                     unsigned long long b) {
    asm("fma.rn.f32x2 %0, %1, %2, %0;" : "+l"(d) : "l"(a), "l"(b));
}
__device__ __forceinline__ void unpack2(float& lo, float& hi,
                                        unsigned long long v) {
    asm("mov.b64 {%0, %1}, %2;" : "=f"(lo), "=f"(hi) : "l"(v));
}
__device__ __forceinline__ unsigned long long bcast2(float v) {
    unsigned long long r;
    asm("mov.b64 %0, {%1, %1};" : "=l"(r) : "f"(v));
    return r;
}

// ---------------- device-wide barrier (all blocks resident) -----------------
__device__ __forceinline__ void gbar_sync(int idx, int target) {
    __syncthreads();
    if (threadIdx.x == 0) {
        asm volatile("red.release.gpu.add.s32 [%0], 1;"
                     :: "l"(&g_bar[idx]) : "memory");
        int v;
        do {
            asm volatile("ld.acquire.gpu.b32 %0, [%1];"
                         : "=r"(v) : "l"(&g_bar[idx]) : "memory");
        } while (v < target);
    }
    __syncthreads();
}

// ---------------- launch 0: persistent CSR build -----------------------------
__global__ void __launch_bounds__(CB_TPB) csrbuild_kernel(const int* __restrict__ ei) {
    int tid = threadIdx.x, bid = blockIdx.x;
    int gt  = bid * CB_TPB + tid;
    int lane = tid & 31, wid = tid >> 5;

    // P0: zero scratch
    if (gt < N_NODES) { g_indeg[gt] = 0; g_cursor[gt] = 0; }
    if (gt < CB_BLOCKS) g_scan_state[gt] = 0;
    gbar_sync(0, CB_BLOCKS);

    // P1: in-degree
    for (int e = gt; e < N_EDGES; e += CB_THREADS)
        atomicAdd(&g_indeg[ei[N_EDGES + e]], 1);
    gbar_sync(1, CB_BLOCKS);

    // P2: scan + dinv (decoupled lookback)
    {
        __shared__ int wsum[8];
        __shared__ int rsum[8];
        __shared__ int sbase;
        int i = gt;
        int v = (i < N_NODES) ? g_indeg[i] : 0;
        if (i < N_NODES) g_dinv[i] = rsqrtf((float)(v + 1));

        int inc = v;
#pragma unroll
        for (int off = 1; off < 32; off <<= 1) {
            int t = __shfl_up_sync(0xffffffffu, inc, off);
            if (lane >= off) inc += t;
        }
        if (lane == 31) wsum[wid] = inc;
        __syncthreads();
        if (wid == 0) {
            int w = (lane < 8) ? wsum[lane] : 0;
#pragma unroll
            for (int off = 1; off < 8; off <<= 1) {
                int t = __shfl_up_sync(0xffffffffu, w, off);
                if (lane >= off) w += t;
            }
            if (lane < 8) wsum[lane] = w;
        }
        __syncthreads();
        int binc  = inc + ((wid > 0) ? wsum[wid - 1] : 0);
        int total = wsum[7];

        if (tid == 0) {
            g_scan_agg[bid] = total;
            asm volatile("st.release.gpu.b32 [%0], %1;"
                         :: "l"(&g_scan_state[bid]), "r"(1) : "memory");
        }
        int part = 0;
        for (int t = tid; t < bid; t += CB_TPB) {
            int st;
            do {
                asm volatile("ld.acquire.gpu.b32 %0, [%1];"
                             : "=r"(st) : "l"(&g_scan_state[t]));
            } while (st == 0);
            part += g_scan_agg[t];
        }
#pragma unroll
        for (int off = 16; off > 0; off >>= 1)
            part += __shfl_down_sync(0xffffffffu, part, off);
        if (lane == 0) rsum[wid] = part;
        __syncthreads();
        if (wid == 0) {
            int t = (lane < 8) ? rsum[lane] : 0;
#pragma unroll
            for (int off = 4; off > 0; off >>= 1)
                t += __shfl_down_sync(0xffffffffu, t, off);
            if (lane == 0) sbase = t;
        }
        __syncthreads();
        int excl = sbase + binc - v;
        if (i < N_NODES) g_offs[i] = excl;
        if (i == N_NODES - 1) g_offs[N_NODES] = excl + v;
    }
    gbar_sync(2, CB_BLOCKS);
    if (gt == 0) { g_bar[0] = 0; g_bar[1] = 0; }

    // P3: CSR fill
#pragma unroll 4
    for (int e = gt; e < N_EDGES; e += CB_THREADS) {
        int s = ei[e];
        int d = ei[N_EDGES + e];
        int p = g_offs[d] + atomicAdd(&g_cursor[d], 1);
        float w = g_dinv[s] * g_dinv[d];
        g_csr[p] = make_int2(s, __float_as_int(w));
    }
}

// ---------------- gather core (warp-wide, lane owns 4 channels) -------------
__device__ __forceinline__ float4 gather_row(const float* __restrict__ hin,
                                             int i, int lane) {
    float di = g_dinv[i];
    float w0 = di * di;
    float4 v = ((const float4*)(hin + (size_t)i * CH))[lane];
    float4 acc = make_float4(v.x * w0, v.y * w0, v.z * w0, v.w * w0);

    int k   = g_offs[i];
    int end = g_offs[i + 1];
    int n   = end - k;
    while (n >= 8) {
        int2 e[8];
#pragma unroll
        for (int q = 0; q < 8; q++) e[q] = g_csr[k + q];
        float4 u[8];
#pragma unroll
        for (int q = 0; q < 8; q++)
            u[q] = ((const float4*)(hin + (size_t)e[q].x * CH))[lane];
#pragma unroll
        for (int q = 0; q < 8; q++) {
            float w = __int_as_float(e[q].y);
            acc.x += w * u[q].x; acc.y += w * u[q].y;
            acc.z += w * u[q].z; acc.w += w * u[q].w;
        }
        k += 8; n -= 8;
    }
    if (n >= 4) {
        int2 e[4];
#pragma unroll
        for (int q = 0; q < 4; q++) e[q] = g_csr[k + q];
        float4 u[4];
#pragma unroll
        for (int q = 0; q < 4; q++)
            u[q] = ((const float4*)(hin + (size_t)e[q].x * CH))[lane];
#pragma unroll
        for (int q = 0; q < 4; q++) {
            float w = __int_as_float(e[q].y);
            acc.x += w * u[q].x; acc.y += w * u[q].y;
            acc.z += w * u[q].z; acc.w += w * u[q].w;
        }
        k += 4; n -= 4;
    }
    if (n >= 2) {
        int2 e0 = g_csr[k], e1 = g_csr[k + 1];
        float4 u0 = ((const float4*)(hin + (size_t)e0.x * CH))[lane];
        float4 u1 = ((const float4*)(hin + (size_t)e1.x * CH))[lane];
        float wa = __int_as_float(e0.y), wb = __int_as_float(e1.y);
        acc.x += wa * u0.x; acc.y += wa * u0.y; acc.z += wa * u0.z; acc.w += wa * u0.w;
        acc.x += wb * u1.x; acc.y += wb * u1.y; acc.z += wb * u1.z; acc.w += wb * u1.w;
        k += 2; n -= 2;
    }
    if (n >= 1) {
        int2 e = g_csr[k];
        float w = __int_as_float(e.y);
        float4 u = ((const float4*)(hin + (size_t)e.x * CH))[lane];
        acc.x += w * u.x; acc.y += w * u.y; acc.z += w * u.z; acc.w += w * u.w;
    }
    return acc;
}

// ---------------- launch 1: hop 1 (warp per node) ---------------------------
__global__ void __launch_bounds__(256) gather_kernel(
        const float* __restrict__ hin, float* __restrict__ hout) {
    if (blockIdx.x == 0 && threadIdx.x == 0) g_bar[2] = 0;  // reset last barrier
    int t = blockIdx.x * blockDim.x + threadIdx.x;
    int i = t >> 5, lane = t & 31;
    if (i >= N_NODES) return;
    float4 acc = gather_row(hin, i, lane);
    ((float4*)(hout + (size_t)i * CH))[lane] = acc;
}

// ---------------- launch 2: fused hop 2 + z = h W^T + b ---------------------
#define GZ_SMEM ((64 * 132 + 128 * 132) * 4)
__global__ void __launch_bounds__(256) gzgemm_kernel(
        const float* __restrict__ hin, const float* __restrict__ W,
        const float* __restrict__ bias, float* __restrict__ C) {
    extern __shared__ float gsm[];
    float* ht = gsm;             // [64][132]  gathered rows
    float* Ws = gsm + 64 * 132;  // [128][132] W transposed: Ws[k][n]
    int tid  = threadIdx.x;
    int m0   = blockIdx.x * 64;
    int lane = tid & 31, wid = tid >> 5;

#pragma unroll
    for (int it = 0; it < 64; it++) {
        int idx = it * 256 + tid;       // 16384 elems
        int n = idx >> 7, k = idx & 127;
        Ws[k * 132 + n] = W[idx];
    }

    for (int q = 0; q < 8; q++) {
        int r = wid * 8 + q;
        int i = m0 + r;
        float4 acc = make_float4(0.f, 0.f, 0.f, 0.f);
        if (i < N_NODES) acc = gather_row(hin, i, lane);
        *(float4*)&ht[r * 132 + lane * 4] = acc;
    }
    __syncthreads();

    int tm = tid >> 4, tn = tid & 15;
    unsigned long long acc2[4][4];
#pragma unroll
    for (int i = 0; i < 4; i++)
#pragma unroll
        for (int j = 0; j < 4; j++) acc2[i][j] = 0ull;

#pragma unroll 2
    for (int k4 = 0; k4 < 32; k4++) {
        float4 av[4];
#pragma unroll
        for (int i = 0; i < 4; i++)
            av[i] = *(const float4*)&ht[(tm * 4 + i) * 132 + k4 * 4];
        ulonglong2 bv[4][2];
#pragma unroll
        for (int kk = 0; kk < 4; kk++) {
            const float* wrow = &Ws[(k4 * 4 + kk) * 132 + tn * 8];
            bv[kk][0] = *(const ulonglong2*)(wrow);
            bv[kk][1] = *(const ulonglong2*)(wrow + 4);
        }
#pragma unroll
        for (int kk = 0; kk < 4; kk++) {
            float a4[4] = { av[0].x, av[1].x, av[2].x, av[3].x };
            if (kk == 1) { a4[0]=av[0].y; a4[1]=av[1].y; a4[2]=av[2].y; a4[3]=av[3].y; }
            if (kk == 2) { a4[0]=av[0].z; a4[1]=av[1].z; a4[2]=av[2].z; a4[3]=av[3].z; }
            if (kk == 3) { a4[0]=av[0].w; a4[1]=av[1].w; a4[2]=av[2].w; a4[3]=av[3].w; }
#pragma unroll
            for (int i = 0; i < 4; i++) {
                unsigned long long a2 = bcast2(a4[i]);
                fma2(acc2[i][0], a2, bv[kk][0].x);
                fma2(acc2[i][1], a2, bv[kk][0].y);
                fma2(acc2[i][2], a2, bv[kk][1].x);
                fma2(acc2[i][3], a2, bv[kk][1].y);
            }
        }
    }
#pragma unroll
    for (int i = 0; i < 4; i++) {
        int row = m0 + tm * 4 + i;
        if (row >= N_NODES) break;
#pragma unroll
        for (int jp = 0; jp < 4; jp++) {
            float lo, hi;
            unpack2(lo, hi, acc2[i][jp]);
            int col = tn * 8 + jp * 2;
            C[(size_t)row * CH + col]     = lo + bias[col];
            C[(size_t)row * CH + col + 1] = hi + bias[col + 1];
        }
    }
}

// ---------------- launch 3: decode -------------------------------------------
// 128 edges/block, 256 threads, thread tile 8 edges x 4 j.
// Broadcast-role swap: te = tid>>4 (warp-uniform pair) so the 8 sv loads are
// broadcasts (1 wf each, EIDX pad de-banks the two addresses); w is stored
// [c4*4+jj][tj] so wv loads are lane-contiguous (256B -> 2 wf, no conflicts).
#define DE 128
#define EIDX(e) ((e) + ((e) >> 3))
#define S4_STRIDE 144
#define DEC_SMEM ((32 * S4_STRIDE + 128 * 16) * 16)   // s4 72KB + w4 32KB = 104KB
#define DEC_BLOCKS ((N_LABEL + DE - 1) / DE)

__global__ void __launch_bounds__(256) decode_kernel(
        const float* __restrict__ z,
        const int* __restrict__ eli,
        const float* __restrict__ w1,
        const float* __restrict__ b1,
        const float* __restrict__ w2,
        const float* __restrict__ b2,
        float* __restrict__ out) {
    extern __shared__ ulonglong2 dsm[];
    ulonglong2* s4 = dsm;                    // [c4][EIDX(e)]
    ulonglong2* w4 = dsm + 32 * S4_STRIDE;   // [(c4*4+jj)][tj 16]
    __shared__ float acc_sm[DE];

    int tid = threadIdx.x;
    int e0  = blockIdx.x * DE;

    // load w1: 2048 float4, 8 per thread.
    // w1v[j*32 + c4] = w1[j][4c4..4c4+3]  ->  w4[(c4*4 + (j&3))*16 + (j>>2)]
    const float4* w1v = (const float4*)w1;
#pragma unroll
    for (int it = 0; it < 8; it++) {
        int idx = it * 256 + tid;
        int j = idx >> 5, c4 = idx & 31;
        ((float4*)w4)[(c4 * 4 + (j & 3)) * 16 + (j >> 2)] = w1v[j * 32 + c4];
    }

    // build s: 2 threads per edge, 16 c4 each
    {
        int ee = tid >> 1, q = tid & 1;
        int e  = e0 + ee;
        int ok = (e < N_LABEL);
        int a  = eli[ok ? e : 0];
        int b  = eli[ok ? (N_LABEL + e) : 0];
        const float4* za4 = (const float4*)(z + (size_t)a * CH);
        const float4* zb4 = (const float4*)(z + (size_t)b * CH);
#pragma unroll
        for (int r = 0; r < 16; r++) {
            int c4 = r * 2 + q;
            float4 x1 = za4[c4], x2 = zb4[c4];
            ((float4*)s4)[c4 * S4_STRIDE + EIDX(ee)] =
                make_float4(x1.x * x2.x, x1.y * x2.y, x1.z * x2.z, x1.w * x2.w);
        }
    }
    if (tid < DE) acc_sm[tid] = b2[0];
    __syncthreads();

    int te = tid >> 4;   // warp-uniform pair: 16 groups x 8 edges = 128
    int tj = tid & 15;   // lane-contiguous:   16 groups x 4 j     = 64
    unsigned long long acc2[8][4];
#pragma unroll
    for (int i = 0; i < 8; i++)
#pragma unroll
        for (int j = 0; j < 4; j++) acc2[i][j] = 0ull;

    // sv base: EIDX(te*8 + ie) = te*9 + ie  (contiguous, broadcast per warp)
#pragma unroll 2
    for (int c4 = 0; c4 < 32; c4++) {
        const ulonglong2* srow = &s4[c4 * S4_STRIDE + te * 9];
        ulonglong2 wv[4];
#pragma unroll
        for (int jj = 0; jj < 4; jj++)
            wv[jj] = w4[(c4 * 4 + jj) * 16 + tj];
        ulonglong2 sv[8];
#pragma unroll
        for (int ie = 0; ie < 8; ie++)
            sv[ie] = srow[ie];
#pragma unroll
        for (int ie = 0; ie < 8; ie++)
#pragma unroll
            for (int jj = 0; jj < 4; jj++) {
                fma2(acc2[ie][jj], sv[ie].x, wv[jj].x);
                fma2(acc2[ie][jj], sv[ie].y, wv[jj].y);
            }
    }

    float p[8] = {0,0,0,0,0,0,0,0};
#pragma unroll
    for (int jj = 0; jj < 4; jj++) {
        int j = tj * 4 + jj;
        float bb = b1[j];
        float ww = w2[j];
#pragma unroll
        for (int ie = 0; ie < 8; ie++) {
            float lo, hi;
            unpack2(lo, hi, acc2[ie][jj]);
            float h = lo + hi + bb;
            if (h > 0.0f) p[ie] += h * ww;
        }
    }
#pragma unroll
    for (int ie = 0; ie < 8; ie++)
        atomicAdd(&acc_sm[te * 8 + ie], p[ie]);
    __syncthreads();

    if (tid < DE && e0 + tid < N_LABEL) out[e0 + tid] = acc_sm[tid];
}

// ---------------- launch ------------------------------------------------------
extern "C" void kernel_launch(void* const* d_in, const int* in_sizes, int n_in,
                              void* d_out, int out_size) {
    const float* x    = (const float*)d_in[0];
    const int*   ei   = (const int*)  d_in[1];
    const int*   eli  = (const int*)  d_in[2];
    const float* cw   = (const float*)d_in[3];
    const float* cb   = (const float*)d_in[4];
    const float* w1   = (const float*)d_in[5];
    const float* b1   = (const float*)d_in[6];
    const float* w2   = (const float*)d_in[7];
    const float* b2   = (const float*)d_in[8];
    float*       out  = (float*)d_out;

    float *hA, *zz;
    cudaGetSymbolAddress((void**)&hA, g_hA);
    cudaGetSymbolAddress((void**)&zz, g_z);

    cudaFuncSetAttribute(gzgemm_kernel,
                         cudaFuncAttributeMaxDynamicSharedMemorySize, GZ_SMEM);
    cudaFuncSetAttribute(decode_kernel,
                         cudaFuncAttributeMaxDynamicSharedMemorySize, DEC_SMEM);

    // 0: CSR build (zero + indeg + scan + fill, persistent)
    csrbuild_kernel<<<CB_BLOCKS, CB_TPB>>>(ei);
    // 1: hop 1
    gather_kernel<<<(N_NODES * 32 + 255) / 256, 256>>>(x, hA);
    // 2: hop 2 fused with z-GEMM
    gzgemm_kernel<<<(N_NODES + 63) / 64, 256, GZ_SMEM>>>(hA, cw, cb, zz);
    // 3: decode  (profiled slot)
    decode_kernel<<<DEC_BLOCKS, 256, DEC_SMEM>>>(zz, eli, w1, b1, w2, b2, out);
}

// round 10
// speedup vs baseline: 1.0505x; 1.0505x over previous
#include <cuda_runtime.h>

#define N_NODES 50000
#define N_EDGES 600000
#define N_LABEL 200000
#define CH      128

#define CB_BLOCKS 196     // 196*256 = 50176 >= N_NODES ; all resident
#define CB_TPB    256
#define CB_THREADS (CB_BLOCKS * CB_TPB)

// ---------------- device scratch (zero at load; self-restoring) -------------
__device__ int   g_bar[3];                 // barrier counters (self-reset)
__device__ int   g_indeg [N_NODES];
__device__ int   g_cursor[N_NODES];
__device__ int   g_scan_state[CB_BLOCKS];
__device__ int   g_scan_agg  [CB_BLOCKS];
__device__ int   g_offs  [N_NODES + 1];
__device__ float g_dinv  [N_NODES];
__device__ int2  g_csr   [N_EDGES];        // .x = src, .y = float bits of w
__device__ float g_hA  [N_NODES * CH];
__device__ float g_z   [N_NODES * CH];

// ---------------- f32x2 packed helpers --------------------------------------
__device__ __forceinline__ void fma2(unsigned long long& d,
                                     unsigned long long a,
                                     unsigned long long b) {
    asm("fma.rn.f32x2 %0, %1, %2, %0;" : "+l"(d) : "l"(a), "l"(b));
}
__device__ __forceinline__ void unpack2(float& lo, float& hi,
                                        unsigned long long v) {
    asm("mov.b64 {%0, %1}, %2;" : "=f"(lo), "=f"(hi) : "l"(v));
}
__device__ __forceinline__ unsigned long long bcast2(float v) {
    unsigned long long r;
    asm("mov.b64 %0, {%1, %1};" : "=l"(r) : "f"(v));
    return r;
}

// ---------------- device-wide barrier (all blocks resident) -----------------
__device__ __forceinline__ void gbar_sync(int idx, int target) {
    __syncthreads();
    if (threadIdx.x == 0) {
        asm volatile("red.release.gpu.add.s32 [%0], 1;"
                     :: "l"(&g_bar[idx]) : "memory");
        int v;
        do {
            asm volatile("ld.acquire.gpu.b32 %0, [%1];"
                         : "=r"(v) : "l"(&g_bar[idx]) : "memory");
        } while (v < target);
    }
    __syncthreads();
}

// ---------------- launch 0: persistent CSR build -----------------------------
__global__ void __launch_bounds__(CB_TPB) csrbuild_kernel(const int* __restrict__ ei) {
    int tid = threadIdx.x, bid = blockIdx.x;
    int gt  = bid * CB_TPB + tid;
    int lane = tid & 31, wid = tid >> 5;

    // P0: zero scratch
    if (gt < N_NODES) { g_indeg[gt] = 0; g_cursor[gt] = 0; }
    if (gt < CB_BLOCKS) g_scan_state[gt] = 0;
    gbar_sync(0, CB_BLOCKS);

    // P1: in-degree
    for (int e = gt; e < N_EDGES; e += CB_THREADS)
        atomicAdd(&g_indeg[ei[N_EDGES + e]], 1);
    gbar_sync(1, CB_BLOCKS);

    // P2: scan + dinv (decoupled lookback)
    {
        __shared__ int wsum[8];
        __shared__ int rsum[8];
        __shared__ int sbase;
        int i = gt;
        int v = (i < N_NODES) ? g_indeg[i] : 0;
        if (i < N_NODES) g_dinv[i] = rsqrtf((float)(v + 1));

        int inc = v;
#pragma unroll
        for (int off = 1; off < 32; off <<= 1) {
            int t = __shfl_up_sync(0xffffffffu, inc, off);
            if (lane >= off) inc += t;
        }
        if (lane == 31) wsum[wid] = inc;
        __syncthreads();
        if (wid == 0) {
            int w = (lane < 8) ? wsum[lane] : 0;
#pragma unroll
            for (int off = 1; off < 8; off <<= 1) {
                int t = __shfl_up_sync(0xffffffffu, w, off);
                if (lane >= off) w += t;
            }
            if (lane < 8) wsum[lane] = w;
        }
        __syncthreads();
        int binc  = inc + ((wid > 0) ? wsum[wid - 1] : 0);
        int total = wsum[7];

        if (tid == 0) {
            g_scan_agg[bid] = total;
            asm volatile("st.release.gpu.b32 [%0], %1;"
                         :: "l"(&g_scan_state[bid]), "r"(1) : "memory");
        }
        int part = 0;
        for (int t = tid; t < bid; t += CB_TPB) {
            int st;
            do {
                asm volatile("ld.acquire.gpu.b32 %0, [%1];"
                             : "=r"(st) : "l"(&g_scan_state[t]));
            } while (st == 0);
            part += g_scan_agg[t];
        }
#pragma unroll
        for (int off = 16; off > 0; off >>= 1)
            part += __shfl_down_sync(0xffffffffu, part, off);
        if (lane == 0) rsum[wid] = part;
        __syncthreads();
        if (wid == 0) {
            int t = (lane < 8) ? rsum[lane] : 0;
#pragma unroll
            for (int off = 4; off > 0; off >>= 1)
                t += __shfl_down_sync(0xffffffffu, t, off);
            if (lane == 0) sbase = t;
        }
        __syncthreads();
        int excl = sbase + binc - v;
        if (i < N_NODES) g_offs[i] = excl;
        if (i == N_NODES - 1) g_offs[N_NODES] = excl + v;
    }
    gbar_sync(2, CB_BLOCKS);
    if (gt == 0) { g_bar[0] = 0; g_bar[1] = 0; }

    // P3: CSR fill
#pragma unroll 4
    for (int e = gt; e < N_EDGES; e += CB_THREADS) {
        int s = ei[e];
        int d = ei[N_EDGES + e];
        int p = g_offs[d] + atomicAdd(&g_cursor[d], 1);
        float w = g_dinv[s] * g_dinv[d];
        g_csr[p] = make_int2(s, __float_as_int(w));
    }
}

// ---------------- gather core (warp-wide, lane owns 4 channels) -------------
__device__ __forceinline__ float4 gather_row(const float* __restrict__ hin,
                                             int i, int lane) {
    float di = g_dinv[i];
    float w0 = di * di;
    float4 v = ((const float4*)(hin + (size_t)i * CH))[lane];
    float4 acc = make_float4(v.x * w0, v.y * w0, v.z * w0, v.w * w0);

    int k   = g_offs[i];
    int end = g_offs[i + 1];
    int n   = end - k;
    while (n >= 8) {
        int2 e[8];
#pragma unroll
        for (int q = 0; q < 8; q++) e[q] = g_csr[k + q];
        float4 u[8];
#pragma unroll
        for (int q = 0; q < 8; q++)
            u[q] = ((const float4*)(hin + (size_t)e[q].x * CH))[lane];
#pragma unroll
        for (int q = 0; q < 8; q++) {
            float w = __int_as_float(e[q].y);
            acc.x += w * u[q].x; acc.y += w * u[q].y;
            acc.z += w * u[q].z; acc.w += w * u[q].w;
        }
        k += 8; n -= 8;
    }
    if (n >= 4) {
        int2 e[4];
#pragma unroll
        for (int q = 0; q < 4; q++) e[q] = g_csr[k + q];
        float4 u[4];
#pragma unroll
        for (int q = 0; q < 4; q++)
            u[q] = ((const float4*)(hin + (size_t)e[q].x * CH))[lane];
#pragma unroll
        for (int q = 0; q < 4; q++) {
            float w = __int_as_float(e[q].y);
            acc.x += w * u[q].x; acc.y += w * u[q].y;
            acc.z += w * u[q].z; acc.w += w * u[q].w;
        }
        k += 4; n -= 4;
    }
    if (n >= 2) {
        int2 e0 = g_csr[k], e1 = g_csr[k + 1];
        float4 u0 = ((const float4*)(hin + (size_t)e0.x * CH))[lane];
        float4 u1 = ((const float4*)(hin + (size_t)e1.x * CH))[lane];
        float wa = __int_as_float(e0.y), wb = __int_as_float(e1.y);
        acc.x += wa * u0.x; acc.y += wa * u0.y; acc.z += wa * u0.z; acc.w += wa * u0.w;
        acc.x += wb * u1.x; acc.y += wb * u1.y; acc.z += wb * u1.z; acc.w += wb * u1.w;
        k += 2; n -= 2;
    }
    if (n >= 1) {
        int2 e = g_csr[k];
        float w = __int_as_float(e.y);
        float4 u = ((const float4*)(hin + (size_t)e.x * CH))[lane];
        acc.x += w * u.x; acc.y += w * u.y; acc.z += w * u.z; acc.w += w * u.w;
    }
    return acc;
}

// ---------------- launch 1: hop 1 (warp per node) ---------------------------
__global__ void __launch_bounds__(256) gather_kernel(
        const float* __restrict__ hin, float* __restrict__ hout) {
    if (blockIdx.x == 0 && threadIdx.x == 0) g_bar[2] = 0;  // reset last barrier
    int t = blockIdx.x * blockDim.x + threadIdx.x;
    int i = t >> 5, lane = t & 31;
    if (i >= N_NODES) return;
    float4 acc = gather_row(hin, i, lane);
    ((float4*)(hout + (size_t)i * CH))[lane] = acc;
}

// ---------------- launch 2: fused hop 2 + z = h W^T + b ---------------------
#define GZ_SMEM ((64 * 132 + 128 * 132) * 4)
__global__ void __launch_bounds__(256) gzgemm_kernel(
        const float* __restrict__ hin, const float* __restrict__ W,
        const float* __restrict__ bias, float* __restrict__ C) {
    extern __shared__ float gsm[];
    float* ht = gsm;             // [64][132]  gathered rows
    float* Ws = gsm + 64 * 132;  // [128][132] W transposed: Ws[k][n]
    int tid  = threadIdx.x;
    int m0   = blockIdx.x * 64;
    int lane = tid & 31, wid = tid >> 5;

#pragma unroll
    for (int it = 0; it < 64; it++) {
        int idx = it * 256 + tid;       // 16384 elems
        int n = idx >> 7, k = idx & 127;
        Ws[k * 132 + n] = W[idx];
    }

    for (int q = 0; q < 8; q++) {
        int r = wid * 8 + q;
        int i = m0 + r;
        float4 acc = make_float4(0.f, 0.f, 0.f, 0.f);
        if (i < N_NODES) acc = gather_row(hin, i, lane);
        *(float4*)&ht[r * 132 + lane * 4] = acc;
    }
    __syncthreads();

    int tm = tid >> 4, tn = tid & 15;
    unsigned long long acc2[4][4];
#pragma unroll
    for (int i = 0; i < 4; i++)
#pragma unroll
        for (int j = 0; j < 4; j++) acc2[i][j] = 0ull;

#pragma unroll 2
    for (int k4 = 0; k4 < 32; k4++) {
        float4 av[4];
#pragma unroll
        for (int i = 0; i < 4; i++)
            av[i] = *(const float4*)&ht[(tm * 4 + i) * 132 + k4 * 4];
        ulonglong2 bv[4][2];
#pragma unroll
        for (int kk = 0; kk < 4; kk++) {
            const float* wrow = &Ws[(k4 * 4 + kk) * 132 + tn * 8];
            bv[kk][0] = *(const ulonglong2*)(wrow);
            bv[kk][1] = *(const ulonglong2*)(wrow + 4);
        }
#pragma unroll
        for (int kk = 0; kk < 4; kk++) {
            float a4[4] = { av[0].x, av[1].x, av[2].x, av[3].x };
            if (kk == 1) { a4[0]=av[0].y; a4[1]=av[1].y; a4[2]=av[2].y; a4[3]=av[3].y; }
            if (kk == 2) { a4[0]=av[0].z; a4[1]=av[1].z; a4[2]=av[2].z; a4[3]=av[3].z; }
            if (kk == 3) { a4[0]=av[0].w; a4[1]=av[1].w; a4[2]=av[2].w; a4[3]=av[3].w; }
#pragma unroll
            for (int i = 0; i < 4; i++) {
                unsigned long long a2 = bcast2(a4[i]);
                fma2(acc2[i][0], a2, bv[kk][0].x);
                fma2(acc2[i][1], a2, bv[kk][0].y);
                fma2(acc2[i][2], a2, bv[kk][1].x);
                fma2(acc2[i][3], a2, bv[kk][1].y);
            }
        }
    }
#pragma unroll
    for (int i = 0; i < 4; i++) {
        int row = m0 + tm * 4 + i;
        if (row >= N_NODES) break;
#pragma unroll
        for (int jp = 0; jp < 4; jp++) {
            float lo, hi;
            unpack2(lo, hi, acc2[i][jp]);
            int col = tn * 8 + jp * 2;
            C[(size_t)row * CH + col]     = lo + bias[col];
            C[(size_t)row * CH + col + 1] = hi + bias[col + 1];
        }
    }
}

// ---------------- launch 3: decode -------------------------------------------
// 128 edges/block, 256 threads, thread tile 8 edges x 4 j (R8 tiling).
// s layout TRANSPOSED for lane-contiguity: slot(e) = (e&7)*18 + (e>>3), so a
// warp's sv load (fixed ie, te=0..15) hits 16 CONSECUTIVE 16B slots = 256B =
// 2 wavefronts, no conflicts. Build mapping re-derived so STS is contiguous.
#define DE 128
#define S4_STRIDE 144          // 8 ie-groups * 18 (16 te + 2 pad)
#define DEC_SMEM ((32 * S4_STRIDE + 32 * 64) * 16)   // s4 72KB + w4 32KB
#define DEC_BLOCKS ((N_LABEL + DE - 1) / DE)

__global__ void __launch_bounds__(256) decode_kernel(
        const float* __restrict__ z,
        const int* __restrict__ eli,
        const float* __restrict__ w1,
        const float* __restrict__ b1,
        const float* __restrict__ w2,
        const float* __restrict__ b2,
        float* __restrict__ out) {
    extern __shared__ ulonglong2 dsm[];
    ulonglong2* s4 = dsm;                    // [c4][slot(e)]
    ulonglong2* w4 = dsm + 32 * S4_STRIDE;   // [c4][j]
    __shared__ float acc_sm[DE];

    int tid = threadIdx.x;
    int e0  = blockIdx.x * DE;

    // load w1: 2048 float4, 8 per thread; w4[c4][j] = w1[j][4c4..4c4+3]
    const float4* w1v = (const float4*)w1;
#pragma unroll
    for (int it = 0; it < 8; it++) {
        int idx = it * 256 + tid;
        int j = idx >> 5, c4 = idx & 31;
        ((float4*)w4)[c4 * 64 + j] = w1v[j * 32 + c4];
    }

    // build s: 2 threads per edge, 16 c4 each.
    // builder ss handles edge ee=(ss&15)*8+(ss>>4), writes slot (ss>>4)*18+(ss&15)
    // -> consecutive ss write consecutive slots (contiguous STS).
    {
        int ss = tid >> 1, q = tid & 1;
        int ee = (ss & 15) * 8 + (ss >> 4);
        int slot = (ss >> 4) * 18 + (ss & 15);
        int e  = e0 + ee;
        int ok = (e < N_LABEL);
        int a  = eli[ok ? e : 0];
        int b  = eli[ok ? (N_LABEL + e) : 0];
        const float4* za4 = (const float4*)(z + (size_t)a * CH);
        const float4* zb4 = (const float4*)(z + (size_t)b * CH);
#pragma unroll
        for (int r = 0; r < 16; r++) {
            int c4 = r * 2 + q;
            float4 x1 = za4[c4], x2 = zb4[c4];
            ((float4*)s4)[c4 * S4_STRIDE + slot] =
                make_float4(x1.x * x2.x, x1.y * x2.y, x1.z * x2.z, x1.w * x2.w);
        }
    }
    if (tid < DE) acc_sm[tid] = b2[0];
    __syncthreads();

    int te = tid & 15;   // 16 groups x 8 edges = 128 (lane-contiguous axis)
    int tj = tid >> 4;   // 16 groups x 4 j     = 64
    unsigned long long acc2[8][4];
#pragma unroll
    for (int i = 0; i < 8; i++)
#pragma unroll
        for (int j = 0; j < 4; j++) acc2[i][j] = 0ull;

    // sv load ie: slot = ie*18 + te -> lanes contiguous in te
#pragma unroll 2
    for (int c4 = 0; c4 < 32; c4++) {
        const ulonglong2* srow = &s4[c4 * S4_STRIDE + te];
        ulonglong2 wv[4];
#pragma unroll
        for (int jj = 0; jj < 4; jj++)
            wv[jj] = w4[c4 * 64 + tj * 4 + jj];
        ulonglong2 sv[8];
#pragma unroll
        for (int ie = 0; ie < 8; ie++)
            sv[ie] = srow[ie * 18];
#pragma unroll
        for (int ie = 0; ie < 8; ie++)
#pragma unroll
            for (int jj = 0; jj < 4; jj++) {
                fma2(acc2[ie][jj], sv[ie].x, wv[jj].x);
                fma2(acc2[ie][jj], sv[ie].y, wv[jj].y);
            }
    }

    float p[8] = {0,0,0,0,0,0,0,0};
#pragma unroll
    for (int jj = 0; jj < 4; jj++) {
        int j = tj * 4 + jj;
        float bb = b1[j];
        float ww = w2[j];
#pragma unroll
        for (int ie = 0; ie < 8; ie++) {
            float lo, hi;
            unpack2(lo, hi, acc2[ie][jj]);
            float h = lo + hi + bb;
            if (h > 0.0f) p[ie] += h * ww;
        }
    }
#pragma unroll
    for (int ie = 0; ie < 8; ie++)
        atomicAdd(&acc_sm[te * 8 + ie], p[ie]);
    __syncthreads();

    if (tid < DE && e0 + tid < N_LABEL) out[e0 + tid] = acc_sm[tid];
}

// ---------------- launch ------------------------------------------------------
extern "C" void kernel_launch(void* const* d_in, const int* in_sizes, int n_in,
                              void* d_out, int out_size) {
    const float* x    = (const float*)d_in[0];
    const int*   ei   = (const int*)  d_in[1];
    const int*   eli  = (const int*)  d_in[2];
    const float* cw   = (const float*)d_in[3];
    const float* cb   = (const float*)d_in[4];
    const float* w1   = (const float*)d_in[5];
    const float* b1   = (const float*)d_in[6];
    const float* w2   = (const float*)d_in[7];
    const float* b2   = (const float*)d_in[8];
    float*       out  = (float*)d_out;

    float *hA, *zz;
    cudaGetSymbolAddress((void**)&hA, g_hA);
    cudaGetSymbolAddress((void**)&zz, g_z);

    cudaFuncSetAttribute(gzgemm_kernel,
                         cudaFuncAttributeMaxDynamicSharedMemorySize, GZ_SMEM);
    cudaFuncSetAttribute(decode_kernel,
                         cudaFuncAttributeMaxDynamicSharedMemorySize, DEC_SMEM);

    // 0: CSR build (zero + indeg + scan + fill, persistent)
    csrbuild_kernel<<<CB_BLOCKS, CB_TPB>>>(ei);
    // 1: hop 1
    gather_kernel<<<(N_NODES * 32 + 255) / 256, 256>>>(x, hA);
    // 2: hop 2 fused with z-GEMM
    gzgemm_kernel<<<(N_NODES + 63) / 64, 256, GZ_SMEM>>>(hA, cw, cb, zz);
    // 3: decode  (profiled slot)
    decode_kernel<<<DEC_BLOCKS, 256, DEC_SMEM>>>(zz, eli, w1, b1, w2, b2, out);
}

// round 13
// speedup vs baseline: 1.2642x; 1.2035x over previous
#include <cuda_runtime.h>
#include <cuda_bf16.h>
#include <cstdint>

#define N_NODES 50000
#define N_EDGES 600000
#define N_LABEL 200000
#define CH      128

#define CB_BLOCKS 196
#define CB_TPB    256
#define CB_THREADS (CB_BLOCKS * CB_TPB)

// ---------------- device scratch --------------------------------------------
__device__ int   g_bar[3];
__device__ int   g_indeg [N_NODES];
__device__ int   g_cursor[N_NODES];
__device__ int   g_scan_state[CB_BLOCKS];
__device__ int   g_scan_agg  [CB_BLOCKS];
__device__ int   g_offs  [N_NODES + 1];
__device__ float g_dinv  [N_NODES];
__device__ int2  g_csr   [N_EDGES];
__device__ float g_hA  [N_NODES * CH];
__device__ float g_z   [N_NODES * CH];

// ---------------- f32x2 helpers ----------------------------------------------
__device__ __forceinline__ void fma2(unsigned long long& d,
                                     unsigned long long a,
                                     unsigned long long b) {
    asm("fma.rn.f32x2 %0, %1, %2, %0;" : "+l"(d) : "l"(a), "l"(b));
}
__device__ __forceinline__ void unpack2(float& lo, float& hi,
                                        unsigned long long v) {
    asm("mov.b64 {%0, %1}, %2;" : "=f"(lo), "=f"(hi) : "l"(v));
}
__device__ __forceinline__ unsigned long long bcast2(float v) {
    unsigned long long r;
    asm("mov.b64 %0, {%1, %1};" : "=l"(r) : "f"(v));
    return r;
}

// ---------------- device-wide barrier ----------------------------------------
__device__ __forceinline__ void gbar_sync(int idx, int target) {
    __syncthreads();
    if (threadIdx.x == 0) {
        asm volatile("red.release.gpu.add.s32 [%0], 1;"
                     :: "l"(&g_bar[idx]) : "memory");
        int v;
        do {
            asm volatile("ld.acquire.gpu.b32 %0, [%1];"
                         : "=r"(v) : "l"(&g_bar[idx]) : "memory");
        } while (v < target);
    }
    __syncthreads();
}

// ---------------- launch 0: persistent CSR build ------------------------------
__global__ void __launch_bounds__(CB_TPB) csrbuild_kernel(const int* __restrict__ ei) {
    int tid = threadIdx.x, bid = blockIdx.x;
    int gt  = bid * CB_TPB + tid;
    int lane = tid & 31, wid = tid >> 5;

    if (gt < N_NODES) { g_indeg[gt] = 0; g_cursor[gt] = 0; }
    if (gt < CB_BLOCKS) g_scan_state[gt] = 0;
    gbar_sync(0, CB_BLOCKS);

    for (int e = gt; e < N_EDGES; e += CB_THREADS)
        atomicAdd(&g_indeg[ei[N_EDGES + e]], 1);
    gbar_sync(1, CB_BLOCKS);

    {
        __shared__ int wsum[8];
        __shared__ int rsum[8];
        __shared__ int sbase;
        int i = gt;
        int v = (i < N_NODES) ? g_indeg[i] : 0;
        if (i < N_NODES) g_dinv[i] = rsqrtf((float)(v + 1));

        int inc = v;
#pragma unroll
        for (int off = 1; off < 32; off <<= 1) {
            int t = __shfl_up_sync(0xffffffffu, inc, off);
            if (lane >= off) inc += t;
        }
        if (lane == 31) wsum[wid] = inc;
        __syncthreads();
        if (wid == 0) {
            int w = (lane < 8) ? wsum[lane] : 0;
#pragma unroll
            for (int off = 1; off < 8; off <<= 1) {
                int t = __shfl_up_sync(0xffffffffu, w, off);
                if (lane >= off) w += t;
            }
            if (lane < 8) wsum[lane] = w;
        }
        __syncthreads();
        int binc  = inc + ((wid > 0) ? wsum[wid - 1] : 0);
        int total = wsum[7];

        if (tid == 0) {
            g_scan_agg[bid] = total;
            asm volatile("st.release.gpu.b32 [%0], %1;"
                         :: "l"(&g_scan_state[bid]), "r"(1) : "memory");
        }
        int part = 0;
        for (int t = tid; t < bid; t += CB_TPB) {
            int st;
            do {
                asm volatile("ld.acquire.gpu.b32 %0, [%1];"
                             : "=r"(st) : "l"(&g_scan_state[t]));
            } while (st == 0);
            part += g_scan_agg[t];
        }
#pragma unroll
        for (int off = 16; off > 0; off >>= 1)
            part += __shfl_down_sync(0xffffffffu, part, off);
        if (lane == 0) rsum[wid] = part;
        __syncthreads();
        if (wid == 0) {
            int t = (lane < 8) ? rsum[lane] : 0;
#pragma unroll
            for (int off = 4; off > 0; off >>= 1)
                t += __shfl_down_sync(0xffffffffu, t, off);
            if (lane == 0) sbase = t;
        }
        __syncthreads();
        int excl = sbase + binc - v;
        if (i < N_NODES) g_offs[i] = excl;
        if (i == N_NODES - 1) g_offs[N_NODES] = excl + v;
    }
    gbar_sync(2, CB_BLOCKS);
    if (gt == 0) { g_bar[0] = 0; g_bar[1] = 0; }

#pragma unroll 4
    for (int e = gt; e < N_EDGES; e += CB_THREADS) {
        int s = ei[e];
        int d = ei[N_EDGES + e];
        int p = g_offs[d] + atomicAdd(&g_cursor[d], 1);
        float w = g_dinv[s] * g_dinv[d];
        g_csr[p] = make_int2(s, __float_as_int(w));
    }
}

// ---------------- gather core -------------------------------------------------
__device__ __forceinline__ float4 gather_row(const float* __restrict__ hin,
                                             int i, int lane) {
    float di = g_dinv[i];
    float w0 = di * di;
    float4 v = ((const float4*)(hin + (size_t)i * CH))[lane];
    float4 acc = make_float4(v.x * w0, v.y * w0, v.z * w0, v.w * w0);

    int k   = g_offs[i];
    int end = g_offs[i + 1];
    int n   = end - k;
    while (n >= 8) {
        int2 e[8];
#pragma unroll
        for (int q = 0; q < 8; q++) e[q] = g_csr[k + q];
        float4 u[8];
#pragma unroll
        for (int q = 0; q < 8; q++)
            u[q] = ((const float4*)(hin + (size_t)e[q].x * CH))[lane];
#pragma unroll
        for (int q = 0; q < 8; q++) {
            float w = __int_as_float(e[q].y);
            acc.x += w * u[q].x; acc.y += w * u[q].y;
            acc.z += w * u[q].z; acc.w += w * u[q].w;
        }
        k += 8; n -= 8;
    }
    if (n >= 4) {
        int2 e[4];
#pragma unroll
        for (int q = 0; q < 4; q++) e[q] = g_csr[k + q];
        float4 u[4];
#pragma unroll
        for (int q = 0; q < 4; q++)
            u[q] = ((const float4*)(hin + (size_t)e[q].x * CH))[lane];
#pragma unroll
        for (int q = 0; q < 4; q++) {
            float w = __int_as_float(e[q].y);
            acc.x += w * u[q].x; acc.y += w * u[q].y;
            acc.z += w * u[q].z; acc.w += w * u[q].w;
        }
        k += 4; n -= 4;
    }
    if (n >= 2) {
        int2 e0 = g_csr[k], e1 = g_csr[k + 1];
        float4 u0 = ((const float4*)(hin + (size_t)e0.x * CH))[lane];
        float4 u1 = ((const float4*)(hin + (size_t)e1.x * CH))[lane];
        float wa = __int_as_float(e0.y), wb = __int_as_float(e1.y);
        acc.x += wa * u0.x; acc.y += wa * u0.y; acc.z += wa * u0.z; acc.w += wa * u0.w;
        acc.x += wb * u1.x; acc.y += wb * u1.y; acc.z += wb * u1.z; acc.w += wb * u1.w;
        k += 2; n -= 2;
    }
    if (n >= 1) {
        int2 e = g_csr[k];
        float w = __int_as_float(e.y);
        float4 u = ((const float4*)(hin + (size_t)e.x * CH))[lane];
        acc.x += w * u.x; acc.y += w * u.y; acc.z += w * u.z; acc.w += w * u.w;
    }
    return acc;
}

// ---------------- launch 1: hop 1 --------------------------------------------
__global__ void __launch_bounds__(256) gather_kernel(
        const float* __restrict__ hin, float* __restrict__ hout) {
    if (blockIdx.x == 0 && threadIdx.x == 0) g_bar[2] = 0;
    int t = blockIdx.x * blockDim.x + threadIdx.x;
    int i = t >> 5, lane = t & 31;
    if (i >= N_NODES) return;
    float4 acc = gather_row(hin, i, lane);
    ((float4*)(hout + (size_t)i * CH))[lane] = acc;
}

// ---------------- launch 2: fused hop 2 + z = h W^T + b ----------------------
#define GZ_SMEM ((64 * 132 + 128 * 132) * 4)
__global__ void __launch_bounds__(256) gzgemm_kernel(
        const float* __restrict__ hin, const float* __restrict__ W,
        const float* __restrict__ bias, float* __restrict__ C) {
    extern __shared__ float gsm[];
    float* ht = gsm;
    float* Ws = gsm + 64 * 132;
    int tid  = threadIdx.x;
    int m0   = blockIdx.x * 64;
    int lane = tid & 31, wid = tid >> 5;

#pragma unroll
    for (int it = 0; it < 64; it++) {
        int idx = it * 256 + tid;
        int n = idx >> 7, k = idx & 127;
        Ws[k * 132 + n] = W[idx];
    }

    for (int q = 0; q < 8; q++) {
        int r = wid * 8 + q;
        int i = m0 + r;
        float4 acc = make_float4(0.f, 0.f, 0.f, 0.f);
        if (i < N_NODES) acc = gather_row(hin, i, lane);
        *(float4*)&ht[r * 132 + lane * 4] = acc;
    }
    __syncthreads();

    int tm = tid >> 4, tn = tid & 15;
    unsigned long long acc2[4][4];
#pragma unroll
    for (int i = 0; i < 4; i++)
#pragma unroll
        for (int j = 0; j < 4; j++) acc2[i][j] = 0ull;

#pragma unroll 2
    for (int k4 = 0; k4 < 32; k4++) {
        float4 av[4];
#pragma unroll
        for (int i = 0; i < 4; i++)
            av[i] = *(const float4*)&ht[(tm * 4 + i) * 132 + k4 * 4];
        ulonglong2 bv[4][2];
#pragma unroll
        for (int kk = 0; kk < 4; kk++) {
            const float* wrow = &Ws[(k4 * 4 + kk) * 132 + tn * 8];
            bv[kk][0] = *(const ulonglong2*)(wrow);
            bv[kk][1] = *(const ulonglong2*)(wrow + 4);
        }
#pragma unroll
        for (int kk = 0; kk < 4; kk++) {
            float a4[4] = { av[0].x, av[1].x, av[2].x, av[3].x };
            if (kk == 1) { a4[0]=av[0].y; a4[1]=av[1].y; a4[2]=av[2].y; a4[3]=av[3].y; }
            if (kk == 2) { a4[0]=av[0].z; a4[1]=av[1].z; a4[2]=av[2].z; a4[3]=av[3].z; }
            if (kk == 3) { a4[0]=av[0].w; a4[1]=av[1].w; a4[2]=av[2].w; a4[3]=av[3].w; }
#pragma unroll
            for (int i = 0; i < 4; i++) {
                unsigned long long a2 = bcast2(a4[i]);
                fma2(acc2[i][0], a2, bv[kk][0].x);
                fma2(acc2[i][1], a2, bv[kk][0].y);
                fma2(acc2[i][2], a2, bv[kk][1].x);
                fma2(acc2[i][3], a2, bv[kk][1].y);
            }
        }
    }
#pragma unroll
    for (int i = 0; i < 4; i++) {
        int row = m0 + tm * 4 + i;
        if (row >= N_NODES) break;
#pragma unroll
        for (int jp = 0; jp < 4; jp++) {
            float lo, hi;
            unpack2(lo, hi, acc2[i][jp]);
            int col = tn * 8 + jp * 2;
            C[(size_t)row * CH + col]     = lo + bias[col];
            C[(size_t)row * CH + col + 1] = hi + bias[col + 1];
        }
    }
}

// ---------------- launch 3: decode via mma.sync bf16 3-term split -------------
// Block: 128 edges, 256 threads (8 warps x 16-edge strips).
// smem: s_hi/s_lo [128][128] bf16 + w_hi/w_lo [64][128] bf16, row stride 136
// bf16 (272 B) -> fragment LDS.32 banks = 4*g+tg (conflict-free).
#define DE 128
#define SROW 272                      // bytes per row (136 bf16)
#define SM_B1  0
#define SM_W2  256
#define SM_SHI 512
#define SM_SLO (SM_SHI + 128 * SROW)
#define SM_WHI (SM_SLO + 128 * SROW)
#define SM_WLO (SM_WHI + 64 * SROW)
#define DEC_SMEM (SM_WLO + 64 * SROW)
#define DEC_BLOCKS ((N_LABEL + DE - 1) / DE)

__device__ __forceinline__ void bf_split4(float4 v, uint2& hp, uint2& lp) {
    __nv_bfloat16 h0 = __float2bfloat16(v.x);
    __nv_bfloat16 h1 = __float2bfloat16(v.y);
    __nv_bfloat16 h2 = __float2bfloat16(v.z);
    __nv_bfloat16 h3 = __float2bfloat16(v.w);
    __nv_bfloat16 l0 = __float2bfloat16(v.x - __bfloat162float(h0));
    __nv_bfloat16 l1 = __float2bfloat16(v.y - __bfloat162float(h1));
    __nv_bfloat16 l2 = __float2bfloat16(v.z - __bfloat162float(h2));
    __nv_bfloat16 l3 = __float2bfloat16(v.w - __bfloat162float(h3));
    hp.x = (uint32_t)__bfloat16_as_ushort(h0) | ((uint32_t)__bfloat16_as_ushort(h1) << 16);
    hp.y = (uint32_t)__bfloat16_as_ushort(h2) | ((uint32_t)__bfloat16_as_ushort(h3) << 16);
    lp.x = (uint32_t)__bfloat16_as_ushort(l0) | ((uint32_t)__bfloat16_as_ushort(l1) << 16);
    lp.y = (uint32_t)__bfloat16_as_ushort(l2) | ((uint32_t)__bfloat16_as_ushort(l3) << 16);
}

__device__ __forceinline__ void mma_bf16(float* d, const uint32_t* a,
                                         uint32_t b0, uint32_t b1) {
    asm volatile(
        "mma.sync.aligned.m16n8k16.row.col.f32.bf16.bf16.f32 "
        "{%0,%1,%2,%3}, {%4,%5,%6,%7}, {%8,%9}, {%0,%1,%2,%3};"
        : "+f"(d[0]), "+f"(d[1]), "+f"(d[2]), "+f"(d[3])
        : "r"(a[0]), "r"(a[1]), "r"(a[2]), "r"(a[3]), "r"(b0), "r"(b1));
}

__global__ void __launch_bounds__(256) decode_kernel(
        const float* __restrict__ z,
        const int* __restrict__ eli,
        const float* __restrict__ w1,
        const float* __restrict__ b1,
        const float* __restrict__ w2,
        const float* __restrict__ b2,
        float* __restrict__ out) {
    extern __shared__ char dsm[];
    int tid = threadIdx.x;
    int wid = tid >> 5, lane = tid & 31;
    int e0  = blockIdx.x * DE;

    if (tid < 64) {
        *(float*)(dsm + SM_B1 + tid * 4) = b1[tid];
        *(float*)(dsm + SM_W2 + tid * 4) = w2[tid];
    }

    // build s hi/lo: 2 threads per edge, 16 c4 chunks each
    {
        int ee = tid >> 1, q = tid & 1;
        int e  = e0 + ee;
        int ok = (e < N_LABEL);
        int a  = eli[ok ? e : 0];
        int b  = eli[ok ? (N_LABEL + e) : 0];
        const float4* za4 = (const float4*)(z + (size_t)a * CH);
        const float4* zb4 = (const float4*)(z + (size_t)b * CH);
#pragma unroll
        for (int r = 0; r < 16; r++) {
            int c4 = r * 2 + q;
            float4 x1 = za4[c4], x2 = zb4[c4];
            float4 s = make_float4(x1.x * x2.x, x1.y * x2.y,
                                   x1.z * x2.z, x1.w * x2.w);
            uint2 hp, lp;
            bf_split4(s, hp, lp);
            int off = ee * SROW + c4 * 8;
            *(uint2*)(dsm + SM_SHI + off) = hp;
            *(uint2*)(dsm + SM_SLO + off) = lp;
        }
    }
    // build w hi/lo: thread -> j = tid>>2, quarter q4 = tid&3 (8 c4 each)
    {
        int j = tid >> 2, q4 = tid & 3;
        const float4* wrow = (const float4*)(w1 + (size_t)j * CH);
#pragma unroll
        for (int r = 0; r < 8; r++) {
            int c4 = r * 4 + q4;
            float4 wv = wrow[c4];
            uint2 hp, lp;
            bf_split4(wv, hp, lp);
            int off = j * SROW + c4 * 8;
            *(uint2*)(dsm + SM_WHI + off) = hp;
            *(uint2*)(dsm + SM_WLO + off) = lp;
        }
    }
    __syncthreads();

    int g  = lane >> 2;      // group 0..7
    int tg = lane & 3;       // thread-in-group
    int ebase = wid * 16;

    float acc[8][4];
#pragma unroll
    for (int nt = 0; nt < 8; nt++)
#pragma unroll
        for (int r = 0; r < 4; r++) acc[nt][r] = 0.f;

    const char* shi = dsm + SM_SHI;
    const char* slo = dsm + SM_SLO;
    const char* whi = dsm + SM_WHI;
    const char* wlo = dsm + SM_WLO;

#pragma unroll
    for (int ks = 0; ks < 8; ks++) {
        int a0off = (ebase + g) * SROW + ks * 32 + tg * 4;
        int a1off = (ebase + g + 8) * SROW + ks * 32 + tg * 4;
        uint32_t ahi[4], alo[4];
        ahi[0] = *(const uint32_t*)(shi + a0off);
        ahi[1] = *(const uint32_t*)(shi + a1off);
        ahi[2] = *(const uint32_t*)(shi + a0off + 16);
        ahi[3] = *(const uint32_t*)(shi + a1off + 16);
        alo[0] = *(const uint32_t*)(slo + a0off);
        alo[1] = *(const uint32_t*)(slo + a1off);
        alo[2] = *(const uint32_t*)(slo + a0off + 16);
        alo[3] = *(const uint32_t*)(slo + a1off + 16);
#pragma unroll
        for (int nt = 0; nt < 8; nt++) {
            int boff = (nt * 8 + g) * SROW + ks * 32 + tg * 4;
            uint32_t bh0 = *(const uint32_t*)(whi + boff);
            uint32_t bh1 = *(const uint32_t*)(whi + boff + 16);
            uint32_t bl0 = *(const uint32_t*)(wlo + boff);
            uint32_t bl1 = *(const uint32_t*)(wlo + boff + 16);
            mma_bf16(acc[nt], ahi, bh0, bh1);
            mma_bf16(acc[nt], ahi, bl0, bl1);
            mma_bf16(acc[nt], alo, bh0, bh1);
        }
    }

    // epilogue: relu + dot(w2); rows g (d0,d1) and g+8 (d2,d3), cols nt*8+tg*2
    float p0 = 0.f, p1 = 0.f;
#pragma unroll
    for (int nt = 0; nt < 8; nt++) {
        int c0 = nt * 8 + tg * 2;
        float bb0 = *(const float*)(dsm + SM_B1 + c0 * 4);
        float bb1 = *(const float*)(dsm + SM_B1 + (c0 + 1) * 4);
        float ww0 = *(const float*)(dsm + SM_W2 + c0 * 4);
        float ww1 = *(const float*)(dsm + SM_W2 + (c0 + 1) * 4);
        float h;
        h = acc[nt][0] + bb0; if (h > 0.f) p0 += h * ww0;
        h = acc[nt][1] + bb1; if (h > 0.f) p0 += h * ww1;
        h = acc[nt][2] + bb0; if (h > 0.f) p1 += h * ww0;
        h = acc[nt][3] + bb1; if (h > 0.f) p1 += h * ww1;
    }
    // reduce over tg (lanes g*4 .. g*4+3)
    p0 += __shfl_xor_sync(0xffffffffu, p0, 1);
    p0 += __shfl_xor_sync(0xffffffffu, p0, 2);
    p1 += __shfl_xor_sync(0xffffffffu, p1, 1);
    p1 += __shfl_xor_sync(0xffffffffu, p1, 2);

    if (tg == 0) {
        float bb = b2[0];
        int r0 = e0 + ebase + g;
        int r1 = r0 + 8;
        if (r0 < N_LABEL) out[r0] = bb + p0;
        if (r1 < N_LABEL) out[r1] = bb + p1;
    }
}

// ---------------- launch ------------------------------------------------------
extern "C" void kernel_launch(void* const* d_in, const int* in_sizes, int n_in,
                              void* d_out, int out_size) {
    const float* x    = (const float*)d_in[0];
    const int*   ei   = (const int*)  d_in[1];
    const int*   eli  = (const int*)  d_in[2];
    const float* cw   = (const float*)d_in[3];
    const float* cb   = (const float*)d_in[4];
    const float* w1   = (const float*)d_in[5];
    const float* b1   = (const float*)d_in[6];
    const float* w2   = (const float*)d_in[7];
    const float* b2   = (const float*)d_in[8];
    float*       out  = (float*)d_out;

    float *hA, *zz;
    cudaGetSymbolAddress((void**)&hA, g_hA);
    cudaGetSymbolAddress((void**)&zz, g_z);

    cudaFuncSetAttribute(gzgemm_kernel,
                         cudaFuncAttributeMaxDynamicSharedMemorySize, GZ_SMEM);
    cudaFuncSetAttribute(decode_kernel,
                         cudaFuncAttributeMaxDynamicSharedMemorySize, DEC_SMEM);

    // 0: CSR build
    csrbuild_kernel<<<CB_BLOCKS, CB_TPB>>>(ei);
    // 1: hop 1
    gather_kernel<<<(N_NODES * 32 + 255) / 256, 256>>>(x, hA);
    // 2: hop 2 fused with z-GEMM
    gzgemm_kernel<<<(N_NODES + 63) / 64, 256, GZ_SMEM>>>(hA, cw, cb, zz);
    // 3: decode (mma.sync bf16, profiled slot)
    decode_kernel<<<DEC_BLOCKS, 256, DEC_SMEM>>>(zz, eli, w1, b1, w2, b2, out);
}

// round 15
// speedup vs baseline: 1.3901x; 1.0995x over previous
#include <cuda_runtime.h>
#include <cuda_bf16.h>
#include <cstdint>

#define N_NODES 50000
#define N_EDGES 600000
#define N_LABEL 200000
#define CH      128

#define CB_BLOCKS 196
#define CB_TPB    256
#define CB_THREADS (CB_BLOCKS * CB_TPB)

// ---------------- device scratch --------------------------------------------
__device__ int   g_bar[3];
__device__ int   g_indeg [N_NODES];
__device__ int   g_cursor[N_NODES];
__device__ int   g_scan_state[CB_BLOCKS];
__device__ int   g_scan_agg  [CB_BLOCKS];
__device__ int   g_offs  [N_NODES + 1];
__device__ float g_dinv  [N_NODES];
__device__ int   g_csr_src[N_EDGES];       // src only (weightless CSR)
__device__ float g_hA  [N_NODES * CH];     // u1 = dinv .* h1
__device__ float g_z   [N_NODES * CH];

// ---------------- f32x2 helpers ----------------------------------------------
__device__ __forceinline__ void fma2(unsigned long long& d,
                                     unsigned long long a,
                                     unsigned long long b) {
    asm("fma.rn.f32x2 %0, %1, %2, %0;" : "+l"(d) : "l"(a), "l"(b));
}
__device__ __forceinline__ void unpack2(float& lo, float& hi,
                                        unsigned long long v) {
    asm("mov.b64 {%0, %1}, %2;" : "=f"(lo), "=f"(hi) : "l"(v));
}
__device__ __forceinline__ unsigned long long bcast2(float v) {
    unsigned long long r;
    asm("mov.b64 %0, {%1, %1};" : "=l"(r) : "f"(v));
    return r;
}

// ---------------- device-wide barrier ----------------------------------------
__device__ __forceinline__ void gbar_sync(int idx, int target) {
    __syncthreads();
    if (threadIdx.x == 0) {
        asm volatile("red.release.gpu.add.s32 [%0], 1;"
                     :: "l"(&g_bar[idx]) : "memory");
        int v;
        do {
            asm volatile("ld.acquire.gpu.b32 %0, [%1];"
                         : "=r"(v) : "l"(&g_bar[idx]) : "memory");
        } while (v < target);
    }
    __syncthreads();
}

// ---------------- launch 0: persistent CSR build ------------------------------
__global__ void __launch_bounds__(CB_TPB) csrbuild_kernel(const int* __restrict__ ei) {
    int tid = threadIdx.x, bid = blockIdx.x;
    int gt  = bid * CB_TPB + tid;
    int lane = tid & 31, wid = tid >> 5;

    if (gt < N_NODES) { g_indeg[gt] = 0; g_cursor[gt] = 0; }
    if (gt < CB_BLOCKS) g_scan_state[gt] = 0;
    gbar_sync(0, CB_BLOCKS);

    for (int e = gt; e < N_EDGES; e += CB_THREADS)
        atomicAdd(&g_indeg[ei[N_EDGES + e]], 1);
    gbar_sync(1, CB_BLOCKS);

    {
        __shared__ int wsum[8];
        __shared__ int rsum[8];
        __shared__ int sbase;
        int i = gt;
        int v = (i < N_NODES) ? g_indeg[i] : 0;
        if (i < N_NODES) g_dinv[i] = rsqrtf((float)(v + 1));

        int inc = v;
#pragma unroll
        for (int off = 1; off < 32; off <<= 1) {
            int t = __shfl_up_sync(0xffffffffu, inc, off);
            if (lane >= off) inc += t;
        }
        if (lane == 31) wsum[wid] = inc;
        __syncthreads();
        if (wid == 0) {
            int w = (lane < 8) ? wsum[lane] : 0;
#pragma unroll
            for (int off = 1; off < 8; off <<= 1) {
                int t = __shfl_up_sync(0xffffffffu, w, off);
                if (lane >= off) w += t;
            }
            if (lane < 8) wsum[lane] = w;
        }
        __syncthreads();
        int binc  = inc + ((wid > 0) ? wsum[wid - 1] : 0);
        int total = wsum[7];

        if (tid == 0) {
            g_scan_agg[bid] = total;
            asm volatile("st.release.gpu.b32 [%0], %1;"
                         :: "l"(&g_scan_state[bid]), "r"(1) : "memory");
        }
        int part = 0;
        for (int t = tid; t < bid; t += CB_TPB) {
            int st;
            do {
                asm volatile("ld.acquire.gpu.b32 %0, [%1];"
                             : "=r"(st) : "l"(&g_scan_state[t]));
            } while (st == 0);
            part += g_scan_agg[t];
        }
#pragma unroll
        for (int off = 16; off > 0; off >>= 1)
            part += __shfl_down_sync(0xffffffffu, part, off);
        if (lane == 0) rsum[wid] = part;
        __syncthreads();
        if (wid == 0) {
            int t = (lane < 8) ? rsum[lane] : 0;
#pragma unroll
            for (int off = 4; off > 0; off >>= 1)
                t += __shfl_down_sync(0xffffffffu, t, off);
            if (lane == 0) sbase = t;
        }
        __syncthreads();
        int excl = sbase + binc - v;
        if (i < N_NODES) g_offs[i] = excl;
        if (i == N_NODES - 1) g_offs[N_NODES] = excl + v;
    }
    gbar_sync(2, CB_BLOCKS);
    if (gt == 0) { g_bar[0] = 0; g_bar[1] = 0; }

    // P3: fill (src index only)
#pragma unroll 4
    for (int e = gt; e < N_EDGES; e += CB_THREADS) {
        int s = ei[e];
        int d = ei[N_EDGES + e];
        int p = g_offs[d] + atomicAdd(&g_cursor[d], 1);
        g_csr_src[p] = s;
    }
}

// ---------------- gather cores -------------------------------------------------
// hop1: inner = dinv_i*x_i + sum dinv_s*x_s ; u1 = dinv_i^2 * inner (= dinv.*h1)
__device__ __forceinline__ float4 gather_row_h1(const float* __restrict__ x,
                                                int i, int lane) {
    float di = g_dinv[i];
    float4 v = ((const float4*)(x + (size_t)i * CH))[lane];
    float4 acc = make_float4(v.x * di, v.y * di, v.z * di, v.w * di);

    int k   = g_offs[i];
    int end = g_offs[i + 1];
    int n   = end - k;
    while (n >= 8) {
        int s[8];
        float ds[8];
#pragma unroll
        for (int q = 0; q < 8; q++) s[q] = g_csr_src[k + q];
#pragma unroll
        for (int q = 0; q < 8; q++) ds[q] = g_dinv[s[q]];
        float4 u[8];
#pragma unroll
        for (int q = 0; q < 8; q++)
            u[q] = ((const float4*)(x + (size_t)s[q] * CH))[lane];
#pragma unroll
        for (int q = 0; q < 8; q++) {
            acc.x += ds[q] * u[q].x; acc.y += ds[q] * u[q].y;
            acc.z += ds[q] * u[q].z; acc.w += ds[q] * u[q].w;
        }
        k += 8; n -= 8;
    }
    while (n > 0) {
        int s = g_csr_src[k];
        float ds = g_dinv[s];
        float4 u = ((const float4*)(x + (size_t)s * CH))[lane];
        acc.x += ds * u.x; acc.y += ds * u.y;
        acc.z += ds * u.z; acc.w += ds * u.w;
        k++; n--;
    }
    float s2 = di * di;   // u1 = dinv * h1 = dinv^2 * inner   (BUGFIX: was di)
    acc.x *= s2; acc.y *= s2; acc.z *= s2; acc.w *= s2;
    return acc;
}

// hop2: input u1 (pre-scaled); out = dinv_i * (u1_i + sum u1_s) = h2
__device__ __forceinline__ float4 gather_row_h2(const float* __restrict__ u1,
                                                int i, int lane) {
    float di = g_dinv[i];
    float4 acc = ((const float4*)(u1 + (size_t)i * CH))[lane];

    int k   = g_offs[i];
    int end = g_offs[i + 1];
    int n   = end - k;
    while (n >= 8) {
        int s[8];
#pragma unroll
        for (int q = 0; q < 8; q++) s[q] = g_csr_src[k + q];
        float4 u[8];
#pragma unroll
        for (int q = 0; q < 8; q++)
            u[q] = ((const float4*)(u1 + (size_t)s[q] * CH))[lane];
#pragma unroll
        for (int q = 0; q < 8; q++) {
            acc.x += u[q].x; acc.y += u[q].y;
            acc.z += u[q].z; acc.w += u[q].w;
        }
        k += 8; n -= 8;
    }
    while (n > 0) {
        int s = g_csr_src[k];
        float4 u = ((const float4*)(u1 + (size_t)s * CH))[lane];
        acc.x += u.x; acc.y += u.y; acc.z += u.z; acc.w += u.w;
        k++; n--;
    }
    acc.x *= di; acc.y *= di; acc.z *= di; acc.w *= di;
    return acc;
}

// ---------------- launch 1: hop 1 --------------------------------------------
__global__ void __launch_bounds__(256) gather_kernel(
        const float* __restrict__ x, float* __restrict__ uout) {
    if (blockIdx.x == 0 && threadIdx.x == 0) g_bar[2] = 0;
    int t = blockIdx.x * blockDim.x + threadIdx.x;
    int i = t >> 5, lane = t & 31;
    if (i >= N_NODES) return;
    float4 acc = gather_row_h1(x, i, lane);
    ((float4*)(uout + (size_t)i * CH))[lane] = acc;
}

// ---------------- launch 2: fused hop 2 + z = h W^T + b ----------------------
#define GZ_SMEM ((64 * 132 + 128 * 132) * 4)
__global__ void __launch_bounds__(256) gzgemm_kernel(
        const float* __restrict__ u1, const float* __restrict__ W,
        const float* __restrict__ bias, float* __restrict__ C) {
    extern __shared__ float gsm[];
    float* ht = gsm;
    float* Ws = gsm + 64 * 132;
    int tid  = threadIdx.x;
    int m0   = blockIdx.x * 64;
    int lane = tid & 31, wid = tid >> 5;

#pragma unroll
    for (int it = 0; it < 64; it++) {
        int idx = it * 256 + tid;
        int n = idx >> 7, k = idx & 127;
        Ws[k * 132 + n] = W[idx];
    }

    for (int q = 0; q < 8; q++) {
        int r = wid * 8 + q;
        int i = m0 + r;
        float4 acc = make_float4(0.f, 0.f, 0.f, 0.f);
        if (i < N_NODES) acc = gather_row_h2(u1, i, lane);
        *(float4*)&ht[r * 132 + lane * 4] = acc;
    }
    __syncthreads();

    int tm = tid >> 4, tn = tid & 15;
    unsigned long long acc2[4][4];
#pragma unroll
    for (int i = 0; i < 4; i++)
#pragma unroll
        for (int j = 0; j < 4; j++) acc2[i][j] = 0ull;

#pragma unroll 2
    for (int k4 = 0; k4 < 32; k4++) {
        float4 av[4];
#pragma unroll
        for (int i = 0; i < 4; i++)
            av[i] = *(const float4*)&ht[(tm * 4 + i) * 132 + k4 * 4];
        ulonglong2 bv[4][2];
#pragma unroll
        for (int kk = 0; kk < 4; kk++) {
            const float* wrow = &Ws[(k4 * 4 + kk) * 132 + tn * 8];
            bv[kk][0] = *(const ulonglong2*)(wrow);
            bv[kk][1] = *(const ulonglong2*)(wrow + 4);
        }
#pragma unroll
        for (int kk = 0; kk < 4; kk++) {
            float a4[4] = { av[0].x, av[1].x, av[2].x, av[3].x };
            if (kk == 1) { a4[0]=av[0].y; a4[1]=av[1].y; a4[2]=av[2].y; a4[3]=av[3].y; }
            if (kk == 2) { a4[0]=av[0].z; a4[1]=av[1].z; a4[2]=av[2].z; a4[3]=av[3].z; }
            if (kk == 3) { a4[0]=av[0].w; a4[1]=av[1].w; a4[2]=av[2].w; a4[3]=av[3].w; }
#pragma unroll
            for (int i = 0; i < 4; i++) {
                unsigned long long a2 = bcast2(a4[i]);
                fma2(acc2[i][0], a2, bv[kk][0].x);
                fma2(acc2[i][1], a2, bv[kk][0].y);
                fma2(acc2[i][2], a2, bv[kk][1].x);
                fma2(acc2[i][3], a2, bv[kk][1].y);
            }
        }
    }
#pragma unroll
    for (int i = 0; i < 4; i++) {
        int row = m0 + tm * 4 + i;
        if (row >= N_NODES) break;
#pragma unroll
        for (int jp = 0; jp < 4; jp++) {
            float lo, hi;
            unpack2(lo, hi, acc2[i][jp]);
            int col = tn * 8 + jp * 2;
            C[(size_t)row * CH + col]     = lo + bias[col];
            C[(size_t)row * CH + col + 1] = hi + bias[col + 1];
        }
    }
}

// ---------------- launch 3: decode (mma.sync bf16, k-split for occupancy) -----
#define DE 128
#define SROW 144                      // 64 bf16 (128B) + 16B pad
#define SM_B1  0
#define SM_W2  256
#define SM_SHI 512
#define SM_SLO (SM_SHI + 128 * SROW)
#define SM_WHI (SM_SLO + 128 * SROW)
#define SM_WLO (SM_WHI + 64 * SROW)
#define DEC_SMEM (SM_WLO + 64 * SROW)   // 55,808 B
#define DEC_BLOCKS ((N_LABEL + DE - 1) / DE)

__device__ __forceinline__ void bf_split4(float4 v, uint2& hp, uint2& lp) {
    __nv_bfloat16 h0 = __float2bfloat16(v.x);
    __nv_bfloat16 h1 = __float2bfloat16(v.y);
    __nv_bfloat16 h2 = __float2bfloat16(v.z);
    __nv_bfloat16 h3 = __float2bfloat16(v.w);
    __nv_bfloat16 l0 = __float2bfloat16(v.x - __bfloat162float(h0));
    __nv_bfloat16 l1 = __float2bfloat16(v.y - __bfloat162float(h1));
    __nv_bfloat16 l2 = __float2bfloat16(v.z - __bfloat162float(h2));
    __nv_bfloat16 l3 = __float2bfloat16(v.w - __bfloat162float(h3));
    hp.x = (uint32_t)__bfloat16_as_ushort(h0) | ((uint32_t)__bfloat16_as_ushort(h1) << 16);
    hp.y = (uint32_t)__bfloat16_as_ushort(h2) | ((uint32_t)__bfloat16_as_ushort(h3) << 16);
    lp.x = (uint32_t)__bfloat16_as_ushort(l0) | ((uint32_t)__bfloat16_as_ushort(l1) << 16);
    lp.y = (uint32_t)__bfloat16_as_ushort(l2) | ((uint32_t)__bfloat16_as_ushort(l3) << 16);
}

__device__ __forceinline__ void mma_bf16(float* d, const uint32_t* a,
                                         uint32_t b0, uint32_t b1) {
    asm volatile(
        "mma.sync.aligned.m16n8k16.row.col.f32.bf16.bf16.f32 "
        "{%0,%1,%2,%3}, {%4,%5,%6,%7}, {%8,%9}, {%0,%1,%2,%3};"
        : "+f"(d[0]), "+f"(d[1]), "+f"(d[2]), "+f"(d[3])
        : "r"(a[0]), "r"(a[1]), "r"(a[2]), "r"(a[3]), "r"(b0), "r"(b1));
}

__global__ void __launch_bounds__(256) decode_kernel(
        const float* __restrict__ z,
        const int* __restrict__ eli,
        const float* __restrict__ w1,
        const float* __restrict__ b1,
        const float* __restrict__ w2,
        const float* __restrict__ b2,
        float* __restrict__ out) {
    extern __shared__ char dsm[];
    int tid = threadIdx.x;
    int wid = tid >> 5, lane = tid & 31;
    int e0  = blockIdx.x * DE;

    if (tid < 64) {
        *(float*)(dsm + SM_B1 + tid * 4) = b1[tid];
        *(float*)(dsm + SM_W2 + tid * 4) = w2[tid];
    }

    // builder roles (hoisted out of the half-loop)
    int ee = tid >> 1, q = tid & 1;
    int e  = e0 + ee;
    int ok = (e < N_LABEL);
    int ea = eli[ok ? e : 0];
    int eb = eli[ok ? (N_LABEL + e) : 0];
    const float4* za4 = (const float4*)(z + (size_t)ea * CH);
    const float4* zb4 = (const float4*)(z + (size_t)eb * CH);
    int wj = tid >> 2, wq = tid & 3;
    const float4* w1v = (const float4*)w1;     // [64][32] float4 view

    int g  = lane >> 2;
    int tg = lane & 3;
    int ebase = wid * 16;

    float acc[8][4];
#pragma unroll
    for (int nt = 0; nt < 8; nt++)
#pragma unroll
        for (int r = 0; r < 4; r++) acc[nt][r] = 0.f;

    const char* shi = dsm + SM_SHI;
    const char* slo = dsm + SM_SLO;
    const char* whi = dsm + SM_WHI;
    const char* wlo = dsm + SM_WLO;

#pragma unroll
    for (int h = 0; h < 2; h++) {
        // build s half: cols h*64 .. h*64+63
#pragma unroll
        for (int r = 0; r < 8; r++) {
            int c4l = r * 2 + q;            // local chunk 0..15
            int c4g = h * 16 + c4l;         // global chunk
            float4 x1 = za4[c4g], x2 = zb4[c4g];
            float4 s = make_float4(x1.x * x2.x, x1.y * x2.y,
                                   x1.z * x2.z, x1.w * x2.w);
            uint2 hp, lp;
            bf_split4(s, hp, lp);
            int off = ee * SROW + c4l * 8;
            *(uint2*)(dsm + SM_SHI + off) = hp;
            *(uint2*)(dsm + SM_SLO + off) = lp;
        }
        // build w half
#pragma unroll
        for (int r = 0; r < 4; r++) {
            int c4l = r * 4 + wq;
            int c4g = h * 16 + c4l;
            float4 wv = w1v[wj * 32 + c4g];
            uint2 hp, lp;
            bf_split4(wv, hp, lp);
            int off = wj * SROW + c4l * 8;
            *(uint2*)(dsm + SM_WHI + off) = hp;
            *(uint2*)(dsm + SM_WLO + off) = lp;
        }
        __syncthreads();

        // mma over 4 local k-steps
#pragma unroll
        for (int ks = 0; ks < 4; ks++) {
            int a0off = (ebase + g) * SROW + ks * 32 + tg * 4;
            int a1off = (ebase + g + 8) * SROW + ks * 32 + tg * 4;
            uint32_t ahi[4], alo[4];
            ahi[0] = *(const uint32_t*)(shi + a0off);
            ahi[1] = *(const uint32_t*)(shi + a1off);
            ahi[2] = *(const uint32_t*)(shi + a0off + 16);
            ahi[3] = *(const uint32_t*)(shi + a1off + 16);
            alo[0] = *(const uint32_t*)(slo + a0off);
            alo[1] = *(const uint32_t*)(slo + a1off);
            alo[2] = *(const uint32_t*)(slo + a0off + 16);
            alo[3] = *(const uint32_t*)(slo + a1off + 16);
#pragma unroll
            for (int nt = 0; nt < 8; nt++) {
                int boff = (nt * 8 + g) * SROW + ks * 32 + tg * 4;
                uint32_t bh0 = *(const uint32_t*)(whi + boff);
                uint32_t bh1 = *(const uint32_t*)(whi + boff + 16);
                uint32_t bl0 = *(const uint32_t*)(wlo + boff);
                uint32_t bl1 = *(const uint32_t*)(wlo + boff + 16);
                mma_bf16(acc[nt], ahi, bh0, bh1);
                mma_bf16(acc[nt], ahi, bl0, bl1);
                mma_bf16(acc[nt], alo, bh0, bh1);
            }
        }
        __syncthreads();   // protect s/w before next half's build
    }

    // epilogue: relu + dot(w2)
    float p0 = 0.f, p1 = 0.f;
#pragma unroll
    for (int nt = 0; nt < 8; nt++) {
        int c0 = nt * 8 + tg * 2;
        float bb0 = *(const float*)(dsm + SM_B1 + c0 * 4);
        float bb1 = *(const float*)(dsm + SM_B1 + (c0 + 1) * 4);
        float ww0 = *(const float*)(dsm + SM_W2 + c0 * 4);
        float ww1 = *(const float*)(dsm + SM_W2 + (c0 + 1) * 4);
        float h;
        h = acc[nt][0] + bb0; if (h > 0.f) p0 += h * ww0;
        h = acc[nt][1] + bb1; if (h > 0.f) p0 += h * ww1;
        h = acc[nt][2] + bb0; if (h > 0.f) p1 += h * ww0;
        h = acc[nt][3] + bb1; if (h > 0.f) p1 += h * ww1;
    }
    p0 += __shfl_xor_sync(0xffffffffu, p0, 1);
    p0 += __shfl_xor_sync(0xffffffffu, p0, 2);
    p1 += __shfl_xor_sync(0xffffffffu, p1, 1);
    p1 += __shfl_xor_sync(0xffffffffu, p1, 2);

    if (tg == 0) {
        float bb = b2[0];
        int r0 = e0 + ebase + g;
        int r1 = r0 + 8;
        if (r0 < N_LABEL) out[r0] = bb + p0;
        if (r1 < N_LABEL) out[r1] = bb + p1;
    }
}

// ---------------- launch ------------------------------------------------------
extern "C" void kernel_launch(void* const* d_in, const int* in_sizes, int n_in,
                              void* d_out, int out_size) {
    const float* x    = (const float*)d_in[0];
    const int*   ei   = (const int*)  d_in[1];
    const int*   eli  = (const int*)  d_in[2];
    const float* cw   = (const float*)d_in[3];
    const float* cb   = (const float*)d_in[4];
    const float* w1   = (const float*)d_in[5];
    const float* b1   = (const float*)d_in[6];
    const float* w2   = (const float*)d_in[7];
    const float* b2   = (const float*)d_in[8];
    float*       out  = (float*)d_out;

    float *hA, *zz;
    cudaGetSymbolAddress((void**)&hA, g_hA);
    cudaGetSymbolAddress((void**)&zz, g_z);

    cudaFuncSetAttribute(gzgemm_kernel,
                         cudaFuncAttributeMaxDynamicSharedMemorySize, GZ_SMEM);
    cudaFuncSetAttribute(decode_kernel,
                         cudaFuncAttributeMaxDynamicSharedMemorySize, DEC_SMEM);

    // 0: CSR build (weightless)
    csrbuild_kernel<<<CB_BLOCKS, CB_TPB>>>(ei);
    // 1: hop 1 (emits u1 = dinv^2 * inner)
    gather_kernel<<<(N_NODES * 32 + 255) / 256, 256>>>(x, hA);
    // 2: hop 2 fused with z-GEMM
    gzgemm_kernel<<<(N_NODES + 63) / 64, 256, GZ_SMEM>>>(hA, cw, cb, zz);
    // 3: decode (mma.sync bf16, k-split; profiled slot)
    decode_kernel<<<DEC_BLOCKS, 256, DEC_SMEM>>>(zz, eli, w1, b1, w2, b2, out);
}